// round 13
// baseline (speedup 1.0000x reference)
#include <cuda_runtime.h>
#include <cuda_fp16.h>
#include <cstdint>

#define NPTS 262144
#define HID  256
#define PPB  32
#define NTHREADS 128

#define C11f 1.0989010989010990f
#define C12f 0.3296703296703297f
#define C33f 0.3846153846153846f

// h-pass weights: [L][tk16][tn32][t32] -> uint4 = (hi b32 pair, lo b32 pair)
__device__ __align__(16) uint4 g_BfH[2][16][32][32];   // 1 MB
// tangent weights: hi only, [L][tk16][tn32][t32] -> uint2
__device__ __align__(16) uint2 g_BfT[2][16][32][32];   // 512 KB

// ---------------- SMEM: acts only ----------------
// 6 arrays x 16384 B: 0 h_hi, 1 h_lo, 2 ax_hi, 3 ax_lo, 4 ay_hi, 5 ay_lo
//   addr: (tk*2+tmm)*512 + (q>>1)*256 + t*8 + (q&1)*4
#define SM_OUT 98304     // float[6][32]
#define SMEM_BYTES 99072

__device__ __forceinline__ void mma16816(float* c, uint32_t a0, uint32_t a1, uint32_t a2, uint32_t a3,
                                         uint32_t b0, uint32_t b1) {
    asm volatile(
        "mma.sync.aligned.m16n8k16.row.col.f32.f16.f16.f32 "
        "{%0,%1,%2,%3},{%4,%5,%6,%7},{%8,%9},{%0,%1,%2,%3};"
        : "+f"(c[0]), "+f"(c[1]), "+f"(c[2]), "+f"(c[3])
        : "r"(a0), "r"(a1), "r"(a2), "r"(a3), "r"(b0), "r"(b1));
}

__device__ __forceinline__ void split2(float v0, float v1, uint32_t& hi, uint32_t& lo) {
    __half h0 = __float2half_rn(v0), h1 = __float2half_rn(v1);
    __half l0 = __float2half_rn(v0 - __half2float(h0));
    __half l1 = __float2half_rn(v1 - __half2float(h1));
    __half2 hh = __halves2half2(h0, h1), ll = __halves2half2(l0, l1);
    hi = *(uint32_t*)&hh;
    lo = *(uint32_t*)&ll;
}

// ---------------- prep: weights -> fragment order, hi/lo split ----------------
__global__ void prep_weights(const float* __restrict__ W2, const float* __restrict__ W3) {
    int L = blockIdx.x >> 8;
    int k = blockIdx.x & 255;
    int n = threadIdx.x;
    float w = (L ? W3 : W2)[k * HID + n];
    __half hi = __float2half_rn(w);
    __half lo = __float2half_rn(w - __half2float(hi));
    int tk = k >> 4, kk = k & 15, tn = n >> 3;
    int t = (n & 7) * 4 + ((kk & 7) >> 1);
    int r = (kk >= 8) ? 1 : 0, hsel = kk & 1;
    int cell = ((L * 16 + tk) * 32 + tn) * 32 + t;
    __half* bh = (__half*)g_BfH;
    bh[cell * 8 + r * 2 + hsel]     = hi;   // hi pair in .x/.y
    bh[cell * 8 + 4 + r * 2 + hsel] = lo;   // lo pair in .z/.w
    __half* bt = (__half*)g_BfT;
    bt[cell * 4 + r * 2 + hsel] = hi;
}

// ---------------- A-fragment loader (arr = hi array index; lo at +16384) ----------------
__device__ __forceinline__ void loadA(const char* smem, int arr, int tk, int tm, int lane,
                                      uint2& a01, uint2& a23, uint2& l01, uint2& l23) {
    const char* pa = smem + arr * 16384 + (tk * 2 + tm) * 512 + lane * 8;
    a01 = *(const uint2*)(pa);
    a23 = *(const uint2*)(pa + 256);
    l01 = *(const uint2*)(pa + 16384);
    l23 = *(const uint2*)(pa + 16384 + 256);
}

// ---------------- main fused kernel ----------------
__global__ void __launch_bounds__(NTHREADS, 2)
pinn_mma(const float* __restrict__ X,
         const float* __restrict__ W1, const float* __restrict__ b1,
         const float* __restrict__ b2, const float* __restrict__ b3,
         const float* __restrict__ Wo, const float* __restrict__ bo,
         float* __restrict__ out)
{
    extern __shared__ char smem[];
    const int tid = threadIdx.x, w = tid >> 5, lane = tid & 31;
    const int tm = w >> 1, nh = w & 1;    // warp: rows tm*16.. , n-half nh*128..
    const int pbase = blockIdx.x * PPB;
    float* so = (float*)(smem + SM_OUT);

    for (int i = tid; i < 192; i += NTHREADS) so[i] = 0.f;

    // ---------------- layer 1 (elementwise, frag-ordered acts) ----------------
    for (int idx = tid; idx < PPB * 128; idx += NTHREADS) {
        int m = idx >> 7, n0 = (idx & 127) * 2;
        float2 xy = ((const float2*)X)[pbase + m];
        float wx0 = W1[n0], wx1 = W1[n0 + 1];
        float wy0 = W1[HID + n0], wy1 = W1[HID + n0 + 1];
        float z0 = fmaf(xy.x, wx0, fmaf(xy.y, wy0, b1[n0]));
        float z1 = fmaf(xy.x, wx1, fmaf(xy.y, wy1, b1[n0 + 1]));
        float h0 = tanhf(z0), h1 = tanhf(z1);
        float g0 = 1.f - h0 * h0, g1 = 1.f - h1 * h1;
        int kk = n0 & 15, tkp = n0 >> 4;
        int tp = (m & 7) * 4 + ((kk & 7) >> 1);
        int q = (((m & 15) >= 8) ? 1 : 0) + ((kk >= 8) ? 2 : 0);
        int off = (tkp * 2 + (m >> 4)) * 512 + (q >> 1) * 256 + tp * 8 + (q & 1) * 4;
        uint32_t hi, lo;
        split2(h0, h1, hi, lo);
        *(uint32_t*)(smem + 0 * 16384 + off) = hi;
        *(uint32_t*)(smem + 1 * 16384 + off) = lo;
        split2(g0 * wx0, g1 * wx1, hi, lo);
        *(uint32_t*)(smem + 2 * 16384 + off) = hi;
        *(uint32_t*)(smem + 3 * 16384 + off) = lo;
        split2(g0 * wy0, g1 * wy1, hi, lo);
        *(uint32_t*)(smem + 4 * 16384 + off) = hi;
        *(uint32_t*)(smem + 5 * 16384 + off) = lo;
    }
    __syncthreads();

    float g[16][4];   // tanh' for this warp's patch, thread-local

#pragma unroll 1
    for (int L = 0; L < 2; L++) {
        const float* bias = L ? b3 : b2;

        // ================= h pass (3-term, B via register-pipelined LDG.128) =================
        {
            float acc[16][4];
#pragma unroll
            for (int j = 0; j < 16; j++)
                acc[j][0] = acc[j][1] = acc[j][2] = acc[j][3] = 0.f;

            const uint4* BH = &g_BfH[L][0][nh * 16][lane];   // stride per tn: 32 uint4; per tk: 1024
            uint4 bA[16], bB[16];
#pragma unroll
            for (int j = 0; j < 16; j++) bA[j] = BH[j * 32];

#pragma unroll 1
            for (int tk = 0; tk < 16; tk += 2) {
                const uint4* p1 = BH + (tk + 1) * 1024;
#pragma unroll
                for (int j = 0; j < 16; j++) bB[j] = p1[j * 32];

                uint2 aH01, aH23, aL01, aL23;
                loadA(smem, 0, tk, tm, lane, aH01, aH23, aL01, aL23);
#pragma unroll
                for (int j = 0; j < 16; j++) {
                    mma16816(acc[j], aH01.x, aH01.y, aH23.x, aH23.y, bA[j].x, bA[j].y);
                    mma16816(acc[j], aH01.x, aH01.y, aH23.x, aH23.y, bA[j].z, bA[j].w);
                    mma16816(acc[j], aL01.x, aL01.y, aL23.x, aL23.y, bA[j].x, bA[j].y);
                }

                if (tk + 2 < 16) {
                    const uint4* p2 = BH + (tk + 2) * 1024;
#pragma unroll
                    for (int j = 0; j < 16; j++) bA[j] = p2[j * 32];
                }
                loadA(smem, 0, tk + 1, tm, lane, aH01, aH23, aL01, aL23);
#pragma unroll
                for (int j = 0; j < 16; j++) {
                    mma16816(acc[j], aH01.x, aH01.y, aH23.x, aH23.y, bB[j].x, bB[j].y);
                    mma16816(acc[j], aH01.x, aH01.y, aH23.x, aH23.y, bB[j].z, bB[j].w);
                    mma16816(acc[j], aL01.x, aL01.y, aL23.x, aL23.y, bB[j].x, bB[j].y);
                }
            }
            __syncthreads();   // mainloop reads done before epilogue writes

            // epilogue
            float pu0 = 0.f, pu1 = 0.f, pv0 = 0.f, pv1 = 0.f;
#pragma unroll
            for (int j = 0; j < 16; j++) {
                int n0 = nh * 128 + j * 8 + 2 * (lane & 3);
                float2 bb = ((const float2*)bias)[n0 >> 1];
                float h0 = tanhf(acc[j][0] + bb.x);
                float h1 = tanhf(acc[j][1] + bb.y);
                float h2 = tanhf(acc[j][2] + bb.x);
                float h3 = tanhf(acc[j][3] + bb.y);
                g[j][0] = 1.f - h0 * h0; g[j][1] = 1.f - h1 * h1;
                g[j][2] = 1.f - h2 * h2; g[j][3] = 1.f - h3 * h3;
                if (L == 0) {
                    int kk = n0 & 15, tkp = n0 >> 4;
                    int qk = (kk >= 8) ? 2 : 0;
                    int offL = (tkp * 2 + tm) * 512 + (qk >> 1) * 256 + lane * 8;
                    uint32_t hi, lo;
                    split2(h0, h1, hi, lo);
                    *(uint32_t*)(smem + 0 * 16384 + offL) = hi;
                    *(uint32_t*)(smem + 1 * 16384 + offL) = lo;
                    split2(h2, h3, hi, lo);
                    *(uint32_t*)(smem + 0 * 16384 + offL + 4) = hi;
                    *(uint32_t*)(smem + 1 * 16384 + offL + 4) = lo;
                } else {
                    float2 wo0 = ((const float2*)Wo)[n0];
                    float2 wo1 = ((const float2*)Wo)[n0 + 1];
                    pu0 += h0 * wo0.x + h1 * wo1.x;  pv0 += h0 * wo0.y + h1 * wo1.y;
                    pu1 += h2 * wo0.x + h3 * wo1.x;  pv1 += h2 * wo0.y + h3 * wo1.y;
                }
            }
            if (L == 1) {
                pu0 += __shfl_xor_sync(~0u, pu0, 1); pu0 += __shfl_xor_sync(~0u, pu0, 2);
                pv0 += __shfl_xor_sync(~0u, pv0, 1); pv0 += __shfl_xor_sync(~0u, pv0, 2);
                pu1 += __shfl_xor_sync(~0u, pu1, 1); pu1 += __shfl_xor_sync(~0u, pu1, 2);
                pv1 += __shfl_xor_sync(~0u, pv1, 1); pv1 += __shfl_xor_sync(~0u, pv1, 2);
                if ((lane & 3) == 0) {
                    int mlo = tm * 16 + (lane >> 2);
                    atomicAdd(&so[0 * 32 + mlo], pu0);
                    atomicAdd(&so[0 * 32 + mlo + 8], pu1);
                    atomicAdd(&so[1 * 32 + mlo], pv0);
                    atomicAdd(&so[1 * 32 + mlo + 8], pv1);
                }
            }
            __syncthreads();
        }

        // ================= tangent pass (2-term, ax & ay fused, hi-only B via LDG.64) =================
        {
            float accx[16][4], accy[16][4];
#pragma unroll
            for (int j = 0; j < 16; j++) {
                accx[j][0] = accx[j][1] = accx[j][2] = accx[j][3] = 0.f;
                accy[j][0] = accy[j][1] = accy[j][2] = accy[j][3] = 0.f;
            }

            const uint2* BT = &g_BfT[L][0][nh * 16][lane];
            uint2 cA[16], cB[16];
#pragma unroll
            for (int j = 0; j < 16; j++) cA[j] = BT[j * 32];

#pragma unroll 1
            for (int tk = 0; tk < 16; tk += 2) {
                const uint2* p1 = BT + (tk + 1) * 1024;
#pragma unroll
                for (int j = 0; j < 16; j++) cB[j] = p1[j * 32];

                uint2 xH01, xH23, xL01, xL23, yH01, yH23, yL01, yL23;
                loadA(smem, 2, tk, tm, lane, xH01, xH23, xL01, xL23);
                loadA(smem, 4, tk, tm, lane, yH01, yH23, yL01, yL23);
#pragma unroll
                for (int j = 0; j < 16; j++) {
                    mma16816(accx[j], xH01.x, xH01.y, xH23.x, xH23.y, cA[j].x, cA[j].y);
                    mma16816(accx[j], xL01.x, xL01.y, xL23.x, xL23.y, cA[j].x, cA[j].y);
                    mma16816(accy[j], yH01.x, yH01.y, yH23.x, yH23.y, cA[j].x, cA[j].y);
                    mma16816(accy[j], yL01.x, yL01.y, yL23.x, yL23.y, cA[j].x, cA[j].y);
                }

                if (tk + 2 < 16) {
                    const uint2* p2 = BT + (tk + 2) * 1024;
#pragma unroll
                    for (int j = 0; j < 16; j++) cA[j] = p2[j * 32];
                }
                loadA(smem, 2, tk + 1, tm, lane, xH01, xH23, xL01, xL23);
                loadA(smem, 4, tk + 1, tm, lane, yH01, yH23, yL01, yL23);
#pragma unroll
                for (int j = 0; j < 16; j++) {
                    mma16816(accx[j], xH01.x, xH01.y, xH23.x, xH23.y, cB[j].x, cB[j].y);
                    mma16816(accx[j], xL01.x, xL01.y, xL23.x, xL23.y, cB[j].x, cB[j].y);
                    mma16816(accy[j], yH01.x, yH01.y, yH23.x, yH23.y, cB[j].x, cB[j].y);
                    mma16816(accy[j], yL01.x, yL01.y, yL23.x, yL23.y, cB[j].x, cB[j].y);
                }
            }
            __syncthreads();   // mainloop reads done before epilogue writes

            // epilogue
            float px0 = 0.f, px1 = 0.f, qx0 = 0.f, qx1 = 0.f;
            float py0 = 0.f, py1 = 0.f, qy0 = 0.f, qy1 = 0.f;
#pragma unroll
            for (int j = 0; j < 16; j++) {
                int n0 = nh * 128 + j * 8 + 2 * (lane & 3);
                float ax0 = g[j][0] * accx[j][0], ax1 = g[j][1] * accx[j][1];
                float ax2 = g[j][2] * accx[j][2], ax3 = g[j][3] * accx[j][3];
                float ay0 = g[j][0] * accy[j][0], ay1 = g[j][1] * accy[j][1];
                float ay2 = g[j][2] * accy[j][2], ay3 = g[j][3] * accy[j][3];
                if (L == 0) {
                    int kk = n0 & 15, tkp = n0 >> 4;
                    int qk = (kk >= 8) ? 2 : 0;
                    int offL = (tkp * 2 + tm) * 512 + (qk >> 1) * 256 + lane * 8;
                    uint32_t hi, lo;
                    split2(ax0, ax1, hi, lo);
                    *(uint32_t*)(smem + 2 * 16384 + offL) = hi;
                    *(uint32_t*)(smem + 3 * 16384 + offL) = lo;
                    split2(ax2, ax3, hi, lo);
                    *(uint32_t*)(smem + 2 * 16384 + offL + 4) = hi;
                    *(uint32_t*)(smem + 3 * 16384 + offL + 4) = lo;
                    split2(ay0, ay1, hi, lo);
                    *(uint32_t*)(smem + 4 * 16384 + offL) = hi;
                    *(uint32_t*)(smem + 5 * 16384 + offL) = lo;
                    split2(ay2, ay3, hi, lo);
                    *(uint32_t*)(smem + 4 * 16384 + offL + 4) = hi;
                    *(uint32_t*)(smem + 5 * 16384 + offL + 4) = lo;
                } else {
                    float2 wo0 = ((const float2*)Wo)[n0];
                    float2 wo1 = ((const float2*)Wo)[n0 + 1];
                    px0 += ax0 * wo0.x + ax1 * wo1.x;  qx0 += ax0 * wo0.y + ax1 * wo1.y;
                    px1 += ax2 * wo0.x + ax3 * wo1.x;  qx1 += ax2 * wo0.y + ax3 * wo1.y;
                    py0 += ay0 * wo0.x + ay1 * wo1.x;  qy0 += ay0 * wo0.y + ay1 * wo1.y;
                    py1 += ay2 * wo0.x + ay3 * wo1.x;  qy1 += ay2 * wo0.y + ay3 * wo1.y;
                }
            }
            if (L == 1) {
#pragma unroll
                for (int off = 1; off <= 2; off <<= 1) {
                    px0 += __shfl_xor_sync(~0u, px0, off); px1 += __shfl_xor_sync(~0u, px1, off);
                    qx0 += __shfl_xor_sync(~0u, qx0, off); qx1 += __shfl_xor_sync(~0u, qx1, off);
                    py0 += __shfl_xor_sync(~0u, py0, off); py1 += __shfl_xor_sync(~0u, py1, off);
                    qy0 += __shfl_xor_sync(~0u, qy0, off); qy1 += __shfl_xor_sync(~0u, qy1, off);
                }
                if ((lane & 3) == 0) {
                    int mlo = tm * 16 + (lane >> 2);
                    atomicAdd(&so[2 * 32 + mlo], px0);  atomicAdd(&so[2 * 32 + mlo + 8], px1);
                    atomicAdd(&so[3 * 32 + mlo], qx0);  atomicAdd(&so[3 * 32 + mlo + 8], qx1);
                    atomicAdd(&so[4 * 32 + mlo], py0);  atomicAdd(&so[4 * 32 + mlo + 8], py1);
                    atomicAdd(&so[5 * 32 + mlo], qy0);  atomicAdd(&so[5 * 32 + mlo + 8], qy1);
                }
            }
            __syncthreads();
        }
    }

    // ---------------- final: stress transform ----------------
    if (tid < PPB) {
        float u   = so[0 * 32 + tid] + bo[0];
        float v   = so[1 * 32 + tid] + bo[1];
        float u_x = so[2 * 32 + tid], v_x = so[3 * 32 + tid];
        float u_y = so[4 * 32 + tid], v_y = so[5 * 32 + tid];
        float u_xy = u_y + v_x;
        float sx  = C11f * u_x + C12f * v_y;
        float sy  = C12f * u_x + C11f * v_y;
        float sxy = C33f * u_xy;
        float sed = 0.5f * (sx * u_x + sy * v_y + sxy * u_xy);
        int p = pbase + tid;
        out[p]            = u;
        out[NPTS + p]     = v;
        out[2 * NPTS + p] = sx;
        out[3 * NPTS + p] = sy;
        out[4 * NPTS + p] = sxy;
        out[5 * NPTS + p] = sed;
    }
}

// ---------------- launcher ----------------
extern "C" void kernel_launch(void* const* d_in, const int* in_sizes, int n_in,
                              void* d_out, int out_size)
{
    const float* X  = (const float*)d_in[0];
    const float* W1 = (const float*)d_in[1];
    const float* b1 = (const float*)d_in[2];
    const float* W2 = (const float*)d_in[3];
    const float* b2 = (const float*)d_in[4];
    const float* W3 = (const float*)d_in[5];
    const float* b3 = (const float*)d_in[6];
    const float* Wo = (const float*)d_in[7];
    const float* bo = (const float*)d_in[8];
    float* out = (float*)d_out;

    static bool attr_set = false;
    if (!attr_set) {
        cudaFuncSetAttribute(pinn_mma, cudaFuncAttributeMaxDynamicSharedMemorySize, SMEM_BYTES);
        attr_set = true;
    }

    prep_weights<<<512, 256>>>(W2, W3);
    pinn_mma<<<NPTS / PPB, NTHREADS, SMEM_BYTES>>>(X, W1, b1, b2, b3, Wo, bo, out);
}

// round 14
// speedup vs baseline: 1.4264x; 1.4264x over previous
#include <cuda_runtime.h>
#include <cuda_fp16.h>
#include <cstdint>

#define NPTS 262144
#define HID  256
#define PPB  32
#define NTHREADS 128

#define C11f 1.0989010989010990f
#define C12f 0.3296703296703297f
#define C33f 0.3846153846153846f

// Weight fragments, frag-ordered: [L][tk16][split(hi/lo)][tn8(32)][t(32)] -> uint2 (4 fp16)
__device__ __align__(16) uint2 g_Bf[2][16][2][32][32];   // 1 MB

// ---------------- SMEM layout (bytes) ----------------
// act arrays (frag order), 16384 B each (32 pts):
//   0 h_hi, 1 h_lo, 2 ax_hi, 3 ax_lo, 4 ay_hi, 5 ay_lo
//   addr: (tk*2+tmm)*512 + (q>>1)*256 + t*8 + (q&1)*4
// B slot: 16 KB at SM_B = two 8 KB double-buffer halves.
#define SM_B   98304
#define SM_OUT 114688     // float[6][32]
#define SMEM_BYTES 115456

__device__ __forceinline__ uint32_t smem_u32(const void* p) {
    uint32_t a;
    asm("{ .reg .u64 t; cvta.to.shared.u64 t, %1; cvt.u32.u64 %0, t; }" : "=r"(a) : "l"(p));
    return a;
}

__device__ __forceinline__ void mma16816(float* c, uint32_t a0, uint32_t a1, uint32_t a2, uint32_t a3,
                                         uint32_t b0, uint32_t b1) {
    asm volatile(
        "mma.sync.aligned.m16n8k16.row.col.f32.f16.f16.f32 "
        "{%0,%1,%2,%3},{%4,%5,%6,%7},{%8,%9},{%0,%1,%2,%3};"
        : "+f"(c[0]), "+f"(c[1]), "+f"(c[2]), "+f"(c[3])
        : "r"(a0), "r"(a1), "r"(a2), "r"(a3), "r"(b0), "r"(b1));
}

__device__ __forceinline__ void split2(float v0, float v1, uint32_t& hi, uint32_t& lo) {
    __half h0 = __float2half_rn(v0), h1 = __float2half_rn(v1);
    __half l0 = __float2half_rn(v0 - __half2float(h0));
    __half l1 = __float2half_rn(v1 - __half2float(h1));
    __half2 hh = __halves2half2(h0, h1), ll = __halves2half2(l0, l1);
    hi = *(uint32_t*)&hh;
    lo = *(uint32_t*)&ll;
}

__device__ __forceinline__ void cpasync16(uint32_t dst, const void* src) {
    asm volatile("cp.async.cg.shared.global [%0], [%1], 16;" :: "r"(dst), "l"(src));
}
#define CP_COMMIT() asm volatile("cp.async.commit_group;" ::: "memory")
#define CP_WAIT0()  asm volatile("cp.async.wait_group 0;" ::: "memory")

// copy one 8KB chunk (split sp of tile tk of layer L) into buffer half `buf`
__device__ __forceinline__ void copy8K(uint32_t sb, int L, int tk, int sp, int buf, int tid) {
    uint32_t dst = sb + SM_B + buf * 8192 + tid * 16;
    const char* src = (const char*)g_Bf + L * 262144 + tk * 16384 + sp * 8192 + tid * 16;
#pragma unroll
    for (int i = 0; i < 4; i++) cpasync16(dst + i * 2048, src + i * 2048);
}

// ---------------- prep: weights -> fragment order, hi/lo split ----------------
__global__ void prep_weights(const float* __restrict__ W2, const float* __restrict__ W3) {
    int L = blockIdx.x >> 8;
    int k = blockIdx.x & 255;
    int n = threadIdx.x;
    float w = (L ? W3 : W2)[k * HID + n];
    __half hi = __float2half_rn(w);
    __half lo = __float2half_rn(w - __half2float(hi));
    int tk = k >> 4, kk = k & 15, tn = n >> 3;
    int t = (n & 7) * 4 + ((kk & 7) >> 1);
    int r = (kk >= 8) ? 1 : 0, hsel = kk & 1;
    __half* base = (__half*)g_Bf;
    int i0 = ((((L * 16 + tk) * 2 + 0) * 32 + tn) * 32 + t) * 4 + r * 2 + hsel;
    int i1 = ((((L * 16 + tk) * 2 + 1) * 32 + tn) * 32 + t) * 4 + r * 2 + hsel;
    base[i0] = hi;
    base[i1] = lo;
}

// ---------------- main fused kernel ----------------
__global__ void __launch_bounds__(NTHREADS, 2)
pinn_mma(const float* __restrict__ X,
         const float* __restrict__ W1, const float* __restrict__ b1,
         const float* __restrict__ b2, const float* __restrict__ b3,
         const float* __restrict__ Wo, const float* __restrict__ bo,
         float* __restrict__ out)
{
    extern __shared__ char smem[];
    const uint32_t sb = smem_u32(smem);
    const int tid = threadIdx.x, w = tid >> 5, lane = tid & 31;
    const int tm = w >> 1, nh = w & 1;    // warp: rows tm*16.. , n-half nh*128..
    const int pbase = blockIdx.x * PPB;
    float* so = (float*)(smem + SM_OUT);

    for (int i = tid; i < 192; i += NTHREADS) so[i] = 0.f;

    // prologue: prefetch L0 tk0 hi into half 0 (overlaps layer 1)
    copy8K(sb, 0, 0, 0, 0, tid);
    CP_COMMIT();

    // ---------------- layer 1 (elementwise, frag-ordered acts) ----------------
    for (int idx = tid; idx < PPB * 128; idx += NTHREADS) {
        int m = idx >> 7, n0 = (idx & 127) * 2;
        float2 xy = ((const float2*)X)[pbase + m];
        float wx0 = W1[n0], wx1 = W1[n0 + 1];
        float wy0 = W1[HID + n0], wy1 = W1[HID + n0 + 1];
        float z0 = fmaf(xy.x, wx0, fmaf(xy.y, wy0, b1[n0]));
        float z1 = fmaf(xy.x, wx1, fmaf(xy.y, wy1, b1[n0 + 1]));
        float h0 = tanhf(z0), h1 = tanhf(z1);
        float g0 = 1.f - h0 * h0, g1 = 1.f - h1 * h1;
        int kk = n0 & 15, tkp = n0 >> 4;
        int tp = (m & 7) * 4 + ((kk & 7) >> 1);
        int q = (((m & 15) >= 8) ? 1 : 0) + ((kk >= 8) ? 2 : 0);
        int off = (tkp * 2 + (m >> 4)) * 512 + (q >> 1) * 256 + tp * 8 + (q & 1) * 4;
        uint32_t hi, lo;
        split2(h0, h1, hi, lo);
        *(uint32_t*)(smem + 0 * 16384 + off) = hi;
        *(uint32_t*)(smem + 1 * 16384 + off) = lo;
        split2(g0 * wx0, g1 * wx1, hi, lo);
        *(uint32_t*)(smem + 2 * 16384 + off) = hi;
        *(uint32_t*)(smem + 3 * 16384 + off) = lo;
        split2(g0 * wy0, g1 * wy1, hi, lo);
        *(uint32_t*)(smem + 4 * 16384 + off) = hi;
        *(uint32_t*)(smem + 5 * 16384 + off) = lo;
    }

    float g[16][4];   // tanh' for this warp's patch, thread-local

#pragma unroll 1
    for (int L = 0; L < 2; L++) {
        const float* bias = L ? b3 : b2;

        // ================= h pass: sweep 1 (AhBh + AlBh over hi chunks), sweep 2 (AhBl over lo) =================
        {
            float acc[16][4];
#pragma unroll
            for (int j = 0; j < 16; j++)
                acc[j][0] = acc[j][1] = acc[j][2] = acc[j][3] = 0.f;

            // ---- sweep 1: hi chunks ----
#pragma unroll 1
            for (int it = 0; it < 16; it++) {
                CP_WAIT0();
                __syncthreads();
                if (it < 15) copy8K(sb, L, it + 1, 0, (it + 1) & 1, tid);
                else         copy8K(sb, L, 0, 1, 0, tid);          // first lo chunk
                CP_COMMIT();

                const char* pa = smem + (it * 2 + tm) * 512 + lane * 8;   // h_hi
                uint2 aH01 = *(const uint2*)(pa);
                uint2 aH23 = *(const uint2*)(pa + 256);
                uint2 aL01 = *(const uint2*)(pa + 16384);
                uint2 aL23 = *(const uint2*)(pa + 16384 + 256);
                const char* pb = smem + SM_B + (it & 1) * 8192 + lane * 8;
                // two-wide interleave: adjacent MMAs hit different accumulators
#pragma unroll
                for (int j = 0; j < 16; j += 2) {
                    int tn = nh * 16 + j;
                    uint2 bH0 = *(const uint2*)(pb + tn * 256);
                    uint2 bH1 = *(const uint2*)(pb + (tn + 1) * 256);
                    mma16816(acc[j],     aH01.x, aH01.y, aH23.x, aH23.y, bH0.x, bH0.y);
                    mma16816(acc[j + 1], aH01.x, aH01.y, aH23.x, aH23.y, bH1.x, bH1.y);
                    mma16816(acc[j],     aL01.x, aL01.y, aL23.x, aL23.y, bH0.x, bH0.y);
                    mma16816(acc[j + 1], aL01.x, aL01.y, aL23.x, aL23.y, bH1.x, bH1.y);
                }
            }
            // ---- sweep 2: lo chunks (1 MMA per j: already independent) ----
#pragma unroll 1
            for (int it = 0; it < 16; it++) {
                CP_WAIT0();
                __syncthreads();
                if (it < 15) copy8K(sb, L, it + 1, 1, (it + 1) & 1, tid);
                else         copy8K(sb, L, 0, 0, 0, tid);          // first tangent (hi) chunk
                CP_COMMIT();

                const char* pa = smem + (it * 2 + tm) * 512 + lane * 8;   // h_hi
                uint2 aH01 = *(const uint2*)(pa);
                uint2 aH23 = *(const uint2*)(pa + 256);
                const char* pb = smem + SM_B + (it & 1) * 8192 + lane * 8;
#pragma unroll
                for (int j = 0; j < 16; j++) {
                    int tn = nh * 16 + j;
                    uint2 bL = *(const uint2*)(pb + tn * 256);
                    mma16816(acc[j], aH01.x, aH01.y, aH23.x, aH23.y, bL.x, bL.y);
                }
            }
            __syncthreads();

            // epilogue
            float pu0 = 0.f, pu1 = 0.f, pv0 = 0.f, pv1 = 0.f;
#pragma unroll
            for (int j = 0; j < 16; j++) {
                int n0 = nh * 128 + j * 8 + 2 * (lane & 3);
                float2 bb = ((const float2*)bias)[n0 >> 1];
                float h0 = tanhf(acc[j][0] + bb.x);
                float h1 = tanhf(acc[j][1] + bb.y);
                float h2 = tanhf(acc[j][2] + bb.x);
                float h3 = tanhf(acc[j][3] + bb.y);
                g[j][0] = 1.f - h0 * h0; g[j][1] = 1.f - h1 * h1;
                g[j][2] = 1.f - h2 * h2; g[j][3] = 1.f - h3 * h3;
                if (L == 0) {
                    int kk = n0 & 15, tkp = n0 >> 4;
                    int qk = (kk >= 8) ? 2 : 0;
                    int offL = (tkp * 2 + tm) * 512 + (qk >> 1) * 256 + lane * 8;
                    uint32_t hi, lo;
                    split2(h0, h1, hi, lo);
                    *(uint32_t*)(smem + 0 * 16384 + offL) = hi;
                    *(uint32_t*)(smem + 1 * 16384 + offL) = lo;
                    split2(h2, h3, hi, lo);
                    *(uint32_t*)(smem + 0 * 16384 + offL + 4) = hi;
                    *(uint32_t*)(smem + 1 * 16384 + offL + 4) = lo;
                } else {
                    float2 wo0 = ((const float2*)Wo)[n0];
                    float2 wo1 = ((const float2*)Wo)[n0 + 1];
                    pu0 += h0 * wo0.x + h1 * wo1.x;  pv0 += h0 * wo0.y + h1 * wo1.y;
                    pu1 += h2 * wo0.x + h3 * wo1.x;  pv1 += h2 * wo0.y + h3 * wo1.y;
                }
            }
            if (L == 1) {
                pu0 += __shfl_xor_sync(~0u, pu0, 1); pu0 += __shfl_xor_sync(~0u, pu0, 2);
                pv0 += __shfl_xor_sync(~0u, pv0, 1); pv0 += __shfl_xor_sync(~0u, pv0, 2);
                pu1 += __shfl_xor_sync(~0u, pu1, 1); pu1 += __shfl_xor_sync(~0u, pu1, 2);
                pv1 += __shfl_xor_sync(~0u, pv1, 1); pv1 += __shfl_xor_sync(~0u, pv1, 2);
                if ((lane & 3) == 0) {
                    int mlo = tm * 16 + (lane >> 2);
                    atomicAdd(&so[0 * 32 + mlo], pu0);
                    atomicAdd(&so[0 * 32 + mlo + 8], pu1);
                    atomicAdd(&so[1 * 32 + mlo], pv0);
                    atomicAdd(&so[1 * 32 + mlo + 8], pv1);
                }
            }
            __syncthreads();
        }

        // ================= tangent pass (2-term, ax & ay fused, hi-only B): 16 its x 8KB =================
        {
            float accx[16][4], accy[16][4];
#pragma unroll
            for (int j = 0; j < 16; j++) {
                accx[j][0] = accx[j][1] = accx[j][2] = accx[j][3] = 0.f;
                accy[j][0] = accy[j][1] = accy[j][2] = accy[j][3] = 0.f;
            }

#pragma unroll 1
            for (int it = 0; it < 16; it++) {
                CP_WAIT0();
                __syncthreads();
                if (it < 15)      copy8K(sb, L, it + 1, 0, (it + 1) & 1, tid);
                else if (L == 0)  copy8K(sb, 1, 0, 0, 0, tid);   // next layer hi chunk0
                CP_COMMIT();

                const char* pa = smem + (it * 2 + tm) * 512 + lane * 8;
                uint2 xH01 = *(const uint2*)(pa + 2 * 16384);
                uint2 xH23 = *(const uint2*)(pa + 2 * 16384 + 256);
                uint2 xL01 = *(const uint2*)(pa + 3 * 16384);
                uint2 xL23 = *(const uint2*)(pa + 3 * 16384 + 256);
                uint2 yH01 = *(const uint2*)(pa + 4 * 16384);
                uint2 yH23 = *(const uint2*)(pa + 4 * 16384 + 256);
                uint2 yL01 = *(const uint2*)(pa + 5 * 16384);
                uint2 yL23 = *(const uint2*)(pa + 5 * 16384 + 256);
                const char* pb = smem + SM_B + (it & 1) * 8192 + lane * 8;
                // two-wide interleave, dep distance 4
#pragma unroll
                for (int j = 0; j < 16; j += 2) {
                    int tn = nh * 16 + j;
                    uint2 bH0 = *(const uint2*)(pb + tn * 256);
                    uint2 bH1 = *(const uint2*)(pb + (tn + 1) * 256);
                    mma16816(accx[j],     xH01.x, xH01.y, xH23.x, xH23.y, bH0.x, bH0.y);
                    mma16816(accx[j + 1], xH01.x, xH01.y, xH23.x, xH23.y, bH1.x, bH1.y);
                    mma16816(accy[j],     yH01.x, yH01.y, yH23.x, yH23.y, bH0.x, bH0.y);
                    mma16816(accy[j + 1], yH01.x, yH01.y, yH23.x, yH23.y, bH1.x, bH1.y);
                    mma16816(accx[j],     xL01.x, xL01.y, xL23.x, xL23.y, bH0.x, bH0.y);
                    mma16816(accx[j + 1], xL01.x, xL01.y, xL23.x, xL23.y, bH1.x, bH1.y);
                    mma16816(accy[j],     yL01.x, yL01.y, yL23.x, yL23.y, bH0.x, bH0.y);
                    mma16816(accy[j + 1], yL01.x, yL01.y, yL23.x, yL23.y, bH1.x, bH1.y);
                }
            }
            __syncthreads();

            // epilogue
            float px0 = 0.f, px1 = 0.f, qx0 = 0.f, qx1 = 0.f;
            float py0 = 0.f, py1 = 0.f, qy0 = 0.f, qy1 = 0.f;
#pragma unroll
            for (int j = 0; j < 16; j++) {
                int n0 = nh * 128 + j * 8 + 2 * (lane & 3);
                float ax0 = g[j][0] * accx[j][0], ax1 = g[j][1] * accx[j][1];
                float ax2 = g[j][2] * accx[j][2], ax3 = g[j][3] * accx[j][3];
                float ay0 = g[j][0] * accy[j][0], ay1 = g[j][1] * accy[j][1];
                float ay2 = g[j][2] * accy[j][2], ay3 = g[j][3] * accy[j][3];
                if (L == 0) {
                    int kk = n0 & 15, tkp = n0 >> 4;
                    int qk = (kk >= 8) ? 2 : 0;
                    int offL = (tkp * 2 + tm) * 512 + (qk >> 1) * 256 + lane * 8;
                    uint32_t hi, lo;
                    split2(ax0, ax1, hi, lo);
                    *(uint32_t*)(smem + 2 * 16384 + offL) = hi;
                    *(uint32_t*)(smem + 3 * 16384 + offL) = lo;
                    split2(ax2, ax3, hi, lo);
                    *(uint32_t*)(smem + 2 * 16384 + offL + 4) = hi;
                    *(uint32_t*)(smem + 3 * 16384 + offL + 4) = lo;
                    split2(ay0, ay1, hi, lo);
                    *(uint32_t*)(smem + 4 * 16384 + offL) = hi;
                    *(uint32_t*)(smem + 5 * 16384 + offL) = lo;
                    split2(ay2, ay3, hi, lo);
                    *(uint32_t*)(smem + 4 * 16384 + offL + 4) = hi;
                    *(uint32_t*)(smem + 5 * 16384 + offL + 4) = lo;
                } else {
                    float2 wo0 = ((const float2*)Wo)[n0];
                    float2 wo1 = ((const float2*)Wo)[n0 + 1];
                    px0 += ax0 * wo0.x + ax1 * wo1.x;  qx0 += ax0 * wo0.y + ax1 * wo1.y;
                    px1 += ax2 * wo0.x + ax3 * wo1.x;  qx1 += ax2 * wo0.y + ax3 * wo1.y;
                    py0 += ay0 * wo0.x + ay1 * wo1.x;  qy0 += ay0 * wo0.y + ay1 * wo1.y;
                    py1 += ay2 * wo0.x + ay3 * wo1.x;  qy1 += ay2 * wo0.y + ay3 * wo1.y;
                }
            }
            if (L == 1) {
#pragma unroll
                for (int off = 1; off <= 2; off <<= 1) {
                    px0 += __shfl_xor_sync(~0u, px0, off); px1 += __shfl_xor_sync(~0u, px1, off);
                    qx0 += __shfl_xor_sync(~0u, qx0, off); qx1 += __shfl_xor_sync(~0u, qx1, off);
                    py0 += __shfl_xor_sync(~0u, py0, off); py1 += __shfl_xor_sync(~0u, py1, off);
                    qy0 += __shfl_xor_sync(~0u, qy0, off); qy1 += __shfl_xor_sync(~0u, qy1, off);
                }
                if ((lane & 3) == 0) {
                    int mlo = tm * 16 + (lane >> 2);
                    atomicAdd(&so[2 * 32 + mlo], px0);  atomicAdd(&so[2 * 32 + mlo + 8], px1);
                    atomicAdd(&so[3 * 32 + mlo], qx0);  atomicAdd(&so[3 * 32 + mlo + 8], qx1);
                    atomicAdd(&so[4 * 32 + mlo], py0);  atomicAdd(&so[4 * 32 + mlo + 8], py1);
                    atomicAdd(&so[5 * 32 + mlo], qy0);  atomicAdd(&so[5 * 32 + mlo + 8], qy1);
                }
            }
            __syncthreads();
        }
    }

    // ---------------- final: stress transform ----------------
    if (tid < PPB) {
        float u   = so[0 * 32 + tid] + bo[0];
        float v   = so[1 * 32 + tid] + bo[1];
        float u_x = so[2 * 32 + tid], v_x = so[3 * 32 + tid];
        float u_y = so[4 * 32 + tid], v_y = so[5 * 32 + tid];
        float u_xy = u_y + v_x;
        float sx  = C11f * u_x + C12f * v_y;
        float sy  = C12f * u_x + C11f * v_y;
        float sxy = C33f * u_xy;
        float sed = 0.5f * (sx * u_x + sy * v_y + sxy * u_xy);
        int p = pbase + tid;
        out[p]            = u;
        out[NPTS + p]     = v;
        out[2 * NPTS + p] = sx;
        out[3 * NPTS + p] = sy;
        out[4 * NPTS + p] = sxy;
        out[5 * NPTS + p] = sed;
    }
}

// ---------------- launcher ----------------
extern "C" void kernel_launch(void* const* d_in, const int* in_sizes, int n_in,
                              void* d_out, int out_size)
{
    const float* X  = (const float*)d_in[0];
    const float* W1 = (const float*)d_in[1];
    const float* b1 = (const float*)d_in[2];
    const float* W2 = (const float*)d_in[3];
    const float* b2 = (const float*)d_in[4];
    const float* W3 = (const float*)d_in[5];
    const float* b3 = (const float*)d_in[6];
    const float* Wo = (const float*)d_in[7];
    const float* bo = (const float*)d_in[8];
    float* out = (float*)d_out;

    static bool attr_set = false;
    if (!attr_set) {
        cudaFuncSetAttribute(pinn_mma, cudaFuncAttributeMaxDynamicSharedMemorySize, SMEM_BYTES);
        attr_set = true;
    }

    prep_weights<<<512, 256>>>(W2, W3);
    pinn_mma<<<NPTS / PPB, NTHREADS, SMEM_BYTES>>>(X, W1, b1, b2, b3, Wo, bo, out);
}

// round 15
// speedup vs baseline: 1.5634x; 1.0961x over previous
#include <cuda_runtime.h>
#include <cuda_fp16.h>
#include <cstdint>

#define NPTS 262144
#define HID  256
#define PPB  32
#define NTHREADS 128

#define C11f 1.0989010989010990f
#define C12f 0.3296703296703297f
#define C33f 0.3846153846153846f

// B fragments: [L][tk16][split(hi/lo)][tn2(16)][t(32)] -> uint4 = frag(tn=2*tn2) ‖ frag(2*tn2+1)
__device__ __align__(16) uint4 g_Bf[2][16][2][16][32];   // 1 MB

// ---------------- SMEM layout (bytes) ----------------
// act arrays, 16384 B each (32 pts): 0 h_hi, 1 h_lo, 2 ax_hi, 3 ax_lo, 4 ay_hi, 5 ay_lo
//   NEW addr: (tk*2+tmm)*512 + t*16 + q*4    (A-frag = one 16B unit per lane)
// B slot: 16 KB at SM_B = two 8 KB double-buffer halves; chunk = [tn2=16][lane=32][16B]
#define SM_B   98304
#define SM_OUT 114688     // float[6][32]
#define SMEM_BYTES 115456

__device__ __forceinline__ uint32_t smem_u32(const void* p) {
    uint32_t a;
    asm("{ .reg .u64 t; cvta.to.shared.u64 t, %1; cvt.u32.u64 %0, t; }" : "=r"(a) : "l"(p));
    return a;
}

__device__ __forceinline__ void mma16816(float* c, uint32_t a0, uint32_t a1, uint32_t a2, uint32_t a3,
                                         uint32_t b0, uint32_t b1) {
    asm volatile(
        "mma.sync.aligned.m16n8k16.row.col.f32.f16.f16.f32 "
        "{%0,%1,%2,%3},{%4,%5,%6,%7},{%8,%9},{%0,%1,%2,%3};"
        : "+f"(c[0]), "+f"(c[1]), "+f"(c[2]), "+f"(c[3])
        : "r"(a0), "r"(a1), "r"(a2), "r"(a3), "r"(b0), "r"(b1));
}

__device__ __forceinline__ void split2(float v0, float v1, uint32_t& hi, uint32_t& lo) {
    __half h0 = __float2half_rn(v0), h1 = __float2half_rn(v1);
    __half l0 = __float2half_rn(v0 - __half2float(h0));
    __half l1 = __float2half_rn(v1 - __half2float(h1));
    __half2 hh = __halves2half2(h0, h1), ll = __halves2half2(l0, l1);
    hi = *(uint32_t*)&hh;
    lo = *(uint32_t*)&ll;
}

__device__ __forceinline__ void cpasync16(uint32_t dst, const void* src) {
    asm volatile("cp.async.cg.shared.global [%0], [%1], 16;" :: "r"(dst), "l"(src));
}
#define CP_COMMIT() asm volatile("cp.async.commit_group;" ::: "memory")
#define CP_WAIT0()  asm volatile("cp.async.wait_group 0;" ::: "memory")

// copy one 8KB chunk (split sp of tile tk of layer L) into buffer half `buf`
__device__ __forceinline__ void copy8K(uint32_t sb, int L, int tk, int sp, int buf, int tid) {
    uint32_t dst = sb + SM_B + buf * 8192 + tid * 16;
    const char* src = (const char*)g_Bf + L * 262144 + tk * 16384 + sp * 8192 + tid * 16;
#pragma unroll
    for (int i = 0; i < 4; i++) cpasync16(dst + i * 2048, src + i * 2048);
}

// ---------------- prep: weights -> paired fragment order, hi/lo split ----------------
__global__ void prep_weights(const float* __restrict__ W2, const float* __restrict__ W3) {
    int L = blockIdx.x >> 8;
    int k = blockIdx.x & 255;
    int n = threadIdx.x;
    float w = (L ? W3 : W2)[k * HID + n];
    __half hi = __float2half_rn(w);
    __half lo = __float2half_rn(w - __half2float(hi));
    int tk = k >> 4, kk = k & 15, tn = n >> 3;
    int t = (n & 7) * 4 + ((kk & 7) >> 1);
    int r = (kk >= 8) ? 1 : 0, hsel = kk & 1;
    __half* base = (__half*)g_Bf;
    // halves index: ((((L*16+tk)*2 + sp)*16 + tn/2)*32 + t)*8 + (tn&1)*4 + r*2 + hsel
    int i0 = ((((L * 16 + tk) * 2 + 0) * 16 + (tn >> 1)) * 32 + t) * 8 + (tn & 1) * 4 + r * 2 + hsel;
    int i1 = ((((L * 16 + tk) * 2 + 1) * 16 + (tn >> 1)) * 32 + t) * 8 + (tn & 1) * 4 + r * 2 + hsel;
    base[i0] = hi;
    base[i1] = lo;
}

// ---------------- main fused kernel ----------------
__global__ void __launch_bounds__(NTHREADS, 2)
pinn_mma(const float* __restrict__ X,
         const float* __restrict__ W1, const float* __restrict__ b1,
         const float* __restrict__ b2, const float* __restrict__ b3,
         const float* __restrict__ Wo, const float* __restrict__ bo,
         float* __restrict__ out)
{
    extern __shared__ char smem[];
    const uint32_t sb = smem_u32(smem);
    const int tid = threadIdx.x, w = tid >> 5, lane = tid & 31;
    const int tm = w >> 1, nh = w & 1;    // warp: rows tm*16.. , n-half nh*128..
    const int pbase = blockIdx.x * PPB;
    float* so = (float*)(smem + SM_OUT);

    for (int i = tid; i < 192; i += NTHREADS) so[i] = 0.f;

    // prologue: prefetch L0 tk0 hi into half 0 (overlaps layer 1)
    copy8K(sb, 0, 0, 0, 0, tid);
    CP_COMMIT();

    // ---------------- layer 1 (elementwise, frag-ordered acts, NEW layout) ----------------
    for (int idx = tid; idx < PPB * 128; idx += NTHREADS) {
        int m = idx >> 7, n0 = (idx & 127) * 2;
        float2 xy = ((const float2*)X)[pbase + m];
        float wx0 = W1[n0], wx1 = W1[n0 + 1];
        float wy0 = W1[HID + n0], wy1 = W1[HID + n0 + 1];
        float z0 = fmaf(xy.x, wx0, fmaf(xy.y, wy0, b1[n0]));
        float z1 = fmaf(xy.x, wx1, fmaf(xy.y, wy1, b1[n0 + 1]));
        float h0 = tanhf(z0), h1 = tanhf(z1);
        float g0 = 1.f - h0 * h0, g1 = 1.f - h1 * h1;
        int kk = n0 & 15, tkp = n0 >> 4;
        int tp = (m & 7) * 4 + ((kk & 7) >> 1);
        int q = (((m & 15) >= 8) ? 1 : 0) + ((kk >= 8) ? 2 : 0);
        int off = (tkp * 2 + (m >> 4)) * 512 + tp * 16 + q * 4;
        uint32_t hi, lo;
        split2(h0, h1, hi, lo);
        *(uint32_t*)(smem + 0 * 16384 + off) = hi;
        *(uint32_t*)(smem + 1 * 16384 + off) = lo;
        split2(g0 * wx0, g1 * wx1, hi, lo);
        *(uint32_t*)(smem + 2 * 16384 + off) = hi;
        *(uint32_t*)(smem + 3 * 16384 + off) = lo;
        split2(g0 * wy0, g1 * wy1, hi, lo);
        *(uint32_t*)(smem + 4 * 16384 + off) = hi;
        *(uint32_t*)(smem + 5 * 16384 + off) = lo;
    }

    float g[16][4];   // tanh' for this warp's patch, thread-local

#pragma unroll 1
    for (int L = 0; L < 2; L++) {
        const float* bias = L ? b3 : b2;

        // ================= h pass: sweep 1 (AhBh + AlBh over hi chunks), sweep 2 (AhBl over lo) =================
        {
            float acc[16][4];
#pragma unroll
            for (int j = 0; j < 16; j++)
                acc[j][0] = acc[j][1] = acc[j][2] = acc[j][3] = 0.f;

            // ---- sweep 1: hi chunks ----
#pragma unroll 1
            for (int it = 0; it < 16; it++) {
                CP_WAIT0();
                __syncthreads();
                if (it < 15) copy8K(sb, L, it + 1, 0, (it + 1) & 1, tid);
                else         copy8K(sb, L, 0, 1, 0, tid);          // first lo chunk
                CP_COMMIT();

                const char* pa = smem + (it * 2 + tm) * 512 + lane * 16;
                uint4 aH = *(const uint4*)(pa);                    // h_hi
                uint4 aL = *(const uint4*)(pa + 16384);            // h_lo
                const char* pb = smem + SM_B + (it & 1) * 8192 + lane * 16;
#pragma unroll
                for (int j2 = 0; j2 < 8; j2++) {
                    uint4 bH = *(const uint4*)(pb + (nh * 8 + j2) * 512);
                    int j = 2 * j2;
                    mma16816(acc[j],     aH.x, aH.y, aH.z, aH.w, bH.x, bH.y);
                    mma16816(acc[j],     aL.x, aL.y, aL.z, aL.w, bH.x, bH.y);
                    mma16816(acc[j + 1], aH.x, aH.y, aH.z, aH.w, bH.z, bH.w);
                    mma16816(acc[j + 1], aL.x, aL.y, aL.z, aL.w, bH.z, bH.w);
                }
            }
            // ---- sweep 2: lo chunks (AhBl) ----
#pragma unroll 1
            for (int it = 0; it < 16; it++) {
                CP_WAIT0();
                __syncthreads();
                if (it < 15) copy8K(sb, L, it + 1, 1, (it + 1) & 1, tid);
                else         copy8K(sb, L, 0, 0, 0, tid);          // first tangent (hi) chunk
                CP_COMMIT();

                const char* pa = smem + (it * 2 + tm) * 512 + lane * 16;
                uint4 aH = *(const uint4*)(pa);                    // h_hi
                const char* pb = smem + SM_B + (it & 1) * 8192 + lane * 16;
#pragma unroll
                for (int j2 = 0; j2 < 8; j2++) {
                    uint4 bL = *(const uint4*)(pb + (nh * 8 + j2) * 512);
                    int j = 2 * j2;
                    mma16816(acc[j],     aH.x, aH.y, aH.z, aH.w, bL.x, bL.y);
                    mma16816(acc[j + 1], aH.x, aH.y, aH.z, aH.w, bL.z, bL.w);
                }
            }
            __syncthreads();

            // epilogue
            float pu0 = 0.f, pu1 = 0.f, pv0 = 0.f, pv1 = 0.f;
#pragma unroll
            for (int j = 0; j < 16; j++) {
                int n0 = nh * 128 + j * 8 + 2 * (lane & 3);
                float2 bb = ((const float2*)bias)[n0 >> 1];
                float h0 = tanhf(acc[j][0] + bb.x);
                float h1 = tanhf(acc[j][1] + bb.y);
                float h2 = tanhf(acc[j][2] + bb.x);
                float h3 = tanhf(acc[j][3] + bb.y);
                g[j][0] = 1.f - h0 * h0; g[j][1] = 1.f - h1 * h1;
                g[j][2] = 1.f - h2 * h2; g[j][3] = 1.f - h3 * h3;
                if (L == 0) {
                    int kk = n0 & 15, tkp = n0 >> 4;
                    int qk = (kk >= 8) ? 2 : 0;
                    int offL = (tkp * 2 + tm) * 512 + lane * 16 + qk * 4;
                    uint32_t hi, lo;
                    split2(h0, h1, hi, lo);
                    *(uint32_t*)(smem + 0 * 16384 + offL) = hi;
                    *(uint32_t*)(smem + 1 * 16384 + offL) = lo;
                    split2(h2, h3, hi, lo);
                    *(uint32_t*)(smem + 0 * 16384 + offL + 4) = hi;
                    *(uint32_t*)(smem + 1 * 16384 + offL + 4) = lo;
                } else {
                    float2 wo0 = ((const float2*)Wo)[n0];
                    float2 wo1 = ((const float2*)Wo)[n0 + 1];
                    pu0 += h0 * wo0.x + h1 * wo1.x;  pv0 += h0 * wo0.y + h1 * wo1.y;
                    pu1 += h2 * wo0.x + h3 * wo1.x;  pv1 += h2 * wo0.y + h3 * wo1.y;
                }
            }
            if (L == 1) {
                pu0 += __shfl_xor_sync(~0u, pu0, 1); pu0 += __shfl_xor_sync(~0u, pu0, 2);
                pv0 += __shfl_xor_sync(~0u, pv0, 1); pv0 += __shfl_xor_sync(~0u, pv0, 2);
                pu1 += __shfl_xor_sync(~0u, pu1, 1); pu1 += __shfl_xor_sync(~0u, pu1, 2);
                pv1 += __shfl_xor_sync(~0u, pv1, 1); pv1 += __shfl_xor_sync(~0u, pv1, 2);
                if ((lane & 3) == 0) {
                    int mlo = tm * 16 + (lane >> 2);
                    atomicAdd(&so[0 * 32 + mlo], pu0);
                    atomicAdd(&so[0 * 32 + mlo + 8], pu1);
                    atomicAdd(&so[1 * 32 + mlo], pv0);
                    atomicAdd(&so[1 * 32 + mlo + 8], pv1);
                }
            }
            __syncthreads();
        }

        // ================= tangent pass (2-term, ax & ay fused, hi-only B): 16 its x 8KB =================
        {
            float accx[16][4], accy[16][4];
#pragma unroll
            for (int j = 0; j < 16; j++) {
                accx[j][0] = accx[j][1] = accx[j][2] = accx[j][3] = 0.f;
                accy[j][0] = accy[j][1] = accy[j][2] = accy[j][3] = 0.f;
            }

#pragma unroll 1
            for (int it = 0; it < 16; it++) {
                CP_WAIT0();
                __syncthreads();
                if (it < 15)      copy8K(sb, L, it + 1, 0, (it + 1) & 1, tid);
                else if (L == 0)  copy8K(sb, 1, 0, 0, 0, tid);   // next layer hi chunk0
                CP_COMMIT();

                const char* pa = smem + (it * 2 + tm) * 512 + lane * 16;
                uint4 xH = *(const uint4*)(pa + 2 * 16384);
                uint4 xL = *(const uint4*)(pa + 3 * 16384);
                uint4 yH = *(const uint4*)(pa + 4 * 16384);
                uint4 yL = *(const uint4*)(pa + 5 * 16384);
                const char* pb = smem + SM_B + (it & 1) * 8192 + lane * 16;
#pragma unroll
                for (int j2 = 0; j2 < 8; j2++) {
                    uint4 bH = *(const uint4*)(pb + (nh * 8 + j2) * 512);
                    int j = 2 * j2;
                    mma16816(accx[j],     xH.x, xH.y, xH.z, xH.w, bH.x, bH.y);
                    mma16816(accx[j],     xL.x, xL.y, xL.z, xL.w, bH.x, bH.y);
                    mma16816(accy[j],     yH.x, yH.y, yH.z, yH.w, bH.x, bH.y);
                    mma16816(accy[j],     yL.x, yL.y, yL.z, yL.w, bH.x, bH.y);
                    mma16816(accx[j + 1], xH.x, xH.y, xH.z, xH.w, bH.z, bH.w);
                    mma16816(accx[j + 1], xL.x, xL.y, xL.z, xL.w, bH.z, bH.w);
                    mma16816(accy[j + 1], yH.x, yH.y, yH.z, yH.w, bH.z, bH.w);
                    mma16816(accy[j + 1], yL.x, yL.y, yL.z, yL.w, bH.z, bH.w);
                }
            }
            __syncthreads();

            // epilogue
            float px0 = 0.f, px1 = 0.f, qx0 = 0.f, qx1 = 0.f;
            float py0 = 0.f, py1 = 0.f, qy0 = 0.f, qy1 = 0.f;
#pragma unroll
            for (int j = 0; j < 16; j++) {
                int n0 = nh * 128 + j * 8 + 2 * (lane & 3);
                float ax0 = g[j][0] * accx[j][0], ax1 = g[j][1] * accx[j][1];
                float ax2 = g[j][2] * accx[j][2], ax3 = g[j][3] * accx[j][3];
                float ay0 = g[j][0] * accy[j][0], ay1 = g[j][1] * accy[j][1];
                float ay2 = g[j][2] * accy[j][2], ay3 = g[j][3] * accy[j][3];
                if (L == 0) {
                    int kk = n0 & 15, tkp = n0 >> 4;
                    int qk = (kk >= 8) ? 2 : 0;
                    int offL = (tkp * 2 + tm) * 512 + lane * 16 + qk * 4;
                    uint32_t hi, lo;
                    split2(ax0, ax1, hi, lo);
                    *(uint32_t*)(smem + 2 * 16384 + offL) = hi;
                    *(uint32_t*)(smem + 3 * 16384 + offL) = lo;
                    split2(ax2, ax3, hi, lo);
                    *(uint32_t*)(smem + 2 * 16384 + offL + 4) = hi;
                    *(uint32_t*)(smem + 3 * 16384 + offL + 4) = lo;
                    split2(ay0, ay1, hi, lo);
                    *(uint32_t*)(smem + 4 * 16384 + offL) = hi;
                    *(uint32_t*)(smem + 5 * 16384 + offL) = lo;
                    split2(ay2, ay3, hi, lo);
                    *(uint32_t*)(smem + 4 * 16384 + offL + 4) = hi;
                    *(uint32_t*)(smem + 5 * 16384 + offL + 4) = lo;
                } else {
                    float2 wo0 = ((const float2*)Wo)[n0];
                    float2 wo1 = ((const float2*)Wo)[n0 + 1];
                    px0 += ax0 * wo0.x + ax1 * wo1.x;  qx0 += ax0 * wo0.y + ax1 * wo1.y;
                    px1 += ax2 * wo0.x + ax3 * wo1.x;  qx1 += ax2 * wo0.y + ax3 * wo1.y;
                    py0 += ay0 * wo0.x + ay1 * wo1.x;  qy0 += ay0 * wo0.y + ay1 * wo1.y;
                    py1 += ay2 * wo0.x + ay3 * wo1.x;  qy1 += ay2 * wo0.y + ay3 * wo1.y;
                }
            }
            if (L == 1) {
#pragma unroll
                for (int off = 1; off <= 2; off <<= 1) {
                    px0 += __shfl_xor_sync(~0u, px0, off); px1 += __shfl_xor_sync(~0u, px1, off);
                    qx0 += __shfl_xor_sync(~0u, qx0, off); qx1 += __shfl_xor_sync(~0u, qx1, off);
                    py0 += __shfl_xor_sync(~0u, py0, off); py1 += __shfl_xor_sync(~0u, py1, off);
                    qy0 += __shfl_xor_sync(~0u, qy0, off); qy1 += __shfl_xor_sync(~0u, qy1, off);
                }
                if ((lane & 3) == 0) {
                    int mlo = tm * 16 + (lane >> 2);
                    atomicAdd(&so[2 * 32 + mlo], px0);  atomicAdd(&so[2 * 32 + mlo + 8], px1);
                    atomicAdd(&so[3 * 32 + mlo], qx0);  atomicAdd(&so[3 * 32 + mlo + 8], qx1);
                    atomicAdd(&so[4 * 32 + mlo], py0);  atomicAdd(&so[4 * 32 + mlo + 8], py1);
                    atomicAdd(&so[5 * 32 + mlo], qy0);  atomicAdd(&so[5 * 32 + mlo + 8], qy1);
                }
            }
            __syncthreads();
        }
    }

    // ---------------- final: stress transform ----------------
    if (tid < PPB) {
        float u   = so[0 * 32 + tid] + bo[0];
        float v   = so[1 * 32 + tid] + bo[1];
        float u_x = so[2 * 32 + tid], v_x = so[3 * 32 + tid];
        float u_y = so[4 * 32 + tid], v_y = so[5 * 32 + tid];
        float u_xy = u_y + v_x;
        float sx  = C11f * u_x + C12f * v_y;
        float sy  = C12f * u_x + C11f * v_y;
        float sxy = C33f * u_xy;
        float sed = 0.5f * (sx * u_x + sy * v_y + sxy * u_xy);
        int p = pbase + tid;
        out[p]            = u;
        out[NPTS + p]     = v;
        out[2 * NPTS + p] = sx;
        out[3 * NPTS + p] = sy;
        out[4 * NPTS + p] = sxy;
        out[5 * NPTS + p] = sed;
    }
}

// ---------------- launcher ----------------
extern "C" void kernel_launch(void* const* d_in, const int* in_sizes, int n_in,
                              void* d_out, int out_size)
{
    const float* X  = (const float*)d_in[0];
    const float* W1 = (const float*)d_in[1];
    const float* b1 = (const float*)d_in[2];
    const float* W2 = (const float*)d_in[3];
    const float* b2 = (const float*)d_in[4];
    const float* W3 = (const float*)d_in[5];
    const float* b3 = (const float*)d_in[6];
    const float* Wo = (const float*)d_in[7];
    const float* bo = (const float*)d_in[8];
    float* out = (float*)d_out;

    static bool attr_set = false;
    if (!attr_set) {
        cudaFuncSetAttribute(pinn_mma, cudaFuncAttributeMaxDynamicSharedMemorySize, SMEM_BYTES);
        attr_set = true;
    }

    prep_weights<<<512, 256>>>(W2, W3);
    pinn_mma<<<NPTS / PPB, NTHREADS, SMEM_BYTES>>>(X, W1, b1, b2, b3, Wo, bo, out);
}

// round 16
// speedup vs baseline: 1.9967x; 1.2771x over previous
#include <cuda_runtime.h>
#include <cuda_fp16.h>
#include <cstdint>

#define NPTS 262144
#define HID  256
#define PPB  32
#define NTHREADS 128

#define C11f 1.0989010989010990f
#define C12f 0.3296703296703297f
#define C33f 0.3846153846153846f

// B fragments: [L][tk16][split(hi/lo)][tn2(16)][t(32)] -> uint4 = frag(2*tn2) ‖ frag(2*tn2+1)
// (lo split retained in memory but unused by the kernel now)
__device__ __align__(16) uint4 g_Bf[2][16][2][16][32];   // 1 MB

// ---------------- SMEM layout (bytes) ----------------
// act arrays, 16384 B each (32 pts): 0 h_hi, 1 h_lo, 2 ax_hi, 3 ax_lo, 4 ay_hi, 5 ay_lo
//   addr: (tk*2+tmm)*512 + t*16 + q*4    (A-frag = one 16B unit per lane)
// B slot: 16 KB at SM_B = two 8 KB double-buffer halves (hi chunks only)
#define SM_B   98304
#define SM_OUT 114688     // float[6][32]
#define SMEM_BYTES 115456

__device__ __forceinline__ uint32_t smem_u32(const void* p) {
    uint32_t a;
    asm("{ .reg .u64 t; cvta.to.shared.u64 t, %1; cvt.u32.u64 %0, t; }" : "=r"(a) : "l"(p));
    return a;
}

__device__ __forceinline__ void mma16816(float* c, uint32_t a0, uint32_t a1, uint32_t a2, uint32_t a3,
                                         uint32_t b0, uint32_t b1) {
    asm volatile(
        "mma.sync.aligned.m16n8k16.row.col.f32.f16.f16.f32 "
        "{%0,%1,%2,%3},{%4,%5,%6,%7},{%8,%9},{%0,%1,%2,%3};"
        : "+f"(c[0]), "+f"(c[1]), "+f"(c[2]), "+f"(c[3])
        : "r"(a0), "r"(a1), "r"(a2), "r"(a3), "r"(b0), "r"(b1));
}

__device__ __forceinline__ void split2(float v0, float v1, uint32_t& hi, uint32_t& lo) {
    __half h0 = __float2half_rn(v0), h1 = __float2half_rn(v1);
    __half l0 = __float2half_rn(v0 - __half2float(h0));
    __half l1 = __float2half_rn(v1 - __half2float(h1));
    __half2 hh = __halves2half2(h0, h1), ll = __halves2half2(l0, l1);
    hi = *(uint32_t*)&hh;
    lo = *(uint32_t*)&ll;
}

__device__ __forceinline__ void cpasync16(uint32_t dst, const void* src) {
    asm volatile("cp.async.cg.shared.global [%0], [%1], 16;" :: "r"(dst), "l"(src));
}
#define CP_COMMIT() asm volatile("cp.async.commit_group;" ::: "memory")
#define CP_WAIT0()  asm volatile("cp.async.wait_group 0;" ::: "memory")

// copy the 8KB hi chunk of tile tk of layer L into buffer half `buf`
__device__ __forceinline__ void copy8K(uint32_t sb, int L, int tk, int buf, int tid) {
    uint32_t dst = sb + SM_B + buf * 8192 + tid * 16;
    const char* src = (const char*)g_Bf + L * 262144 + tk * 16384 + tid * 16;
#pragma unroll
    for (int i = 0; i < 4; i++) cpasync16(dst + i * 2048, src + i * 2048);
}

// ---------------- prep: weights -> paired fragment order, hi/lo split ----------------
__global__ void prep_weights(const float* __restrict__ W2, const float* __restrict__ W3) {
    int L = blockIdx.x >> 8;
    int k = blockIdx.x & 255;
    int n = threadIdx.x;
    float w = (L ? W3 : W2)[k * HID + n];
    __half hi = __float2half_rn(w);
    __half lo = __float2half_rn(w - __half2float(hi));
    int tk = k >> 4, kk = k & 15, tn = n >> 3;
    int t = (n & 7) * 4 + ((kk & 7) >> 1);
    int r = (kk >= 8) ? 1 : 0, hsel = kk & 1;
    __half* base = (__half*)g_Bf;
    int i0 = ((((L * 16 + tk) * 2 + 0) * 16 + (tn >> 1)) * 32 + t) * 8 + (tn & 1) * 4 + r * 2 + hsel;
    int i1 = ((((L * 16 + tk) * 2 + 1) * 16 + (tn >> 1)) * 32 + t) * 8 + (tn & 1) * 4 + r * 2 + hsel;
    base[i0] = hi;
    base[i1] = lo;
}

// ---------------- main fused kernel ----------------
__global__ void __launch_bounds__(NTHREADS, 2)
pinn_mma(const float* __restrict__ X,
         const float* __restrict__ W1, const float* __restrict__ b1,
         const float* __restrict__ b2, const float* __restrict__ b3,
         const float* __restrict__ Wo, const float* __restrict__ bo,
         float* __restrict__ out)
{
    extern __shared__ char smem[];
    const uint32_t sb = smem_u32(smem);
    const int tid = threadIdx.x, w = tid >> 5, lane = tid & 31;
    const int tm = w >> 1, nh = w & 1;    // warp: rows tm*16.. , n-half nh*128..
    const int pbase = blockIdx.x * PPB;
    float* so = (float*)(smem + SM_OUT);

    for (int i = tid; i < 192; i += NTHREADS) so[i] = 0.f;

    // prologue: prefetch L0 tk0 hi into half 0 (overlaps layer 1)
    copy8K(sb, 0, 0, 0, tid);
    CP_COMMIT();

    // ---------------- layer 1 (elementwise, frag-ordered acts) ----------------
    for (int idx = tid; idx < PPB * 128; idx += NTHREADS) {
        int m = idx >> 7, n0 = (idx & 127) * 2;
        float2 xy = ((const float2*)X)[pbase + m];
        float wx0 = W1[n0], wx1 = W1[n0 + 1];
        float wy0 = W1[HID + n0], wy1 = W1[HID + n0 + 1];
        float z0 = fmaf(xy.x, wx0, fmaf(xy.y, wy0, b1[n0]));
        float z1 = fmaf(xy.x, wx1, fmaf(xy.y, wy1, b1[n0 + 1]));
        float h0 = tanhf(z0), h1 = tanhf(z1);
        float g0 = 1.f - h0 * h0, g1 = 1.f - h1 * h1;
        int kk = n0 & 15, tkp = n0 >> 4;
        int tp = (m & 7) * 4 + ((kk & 7) >> 1);
        int q = (((m & 15) >= 8) ? 1 : 0) + ((kk >= 8) ? 2 : 0);
        int off = (tkp * 2 + (m >> 4)) * 512 + tp * 16 + q * 4;
        uint32_t hi, lo;
        split2(h0, h1, hi, lo);
        *(uint32_t*)(smem + 0 * 16384 + off) = hi;
        *(uint32_t*)(smem + 1 * 16384 + off) = lo;
        split2(g0 * wx0, g1 * wx1, hi, lo);
        *(uint32_t*)(smem + 2 * 16384 + off) = hi;
        *(uint32_t*)(smem + 3 * 16384 + off) = lo;
        split2(g0 * wy0, g1 * wy1, hi, lo);
        *(uint32_t*)(smem + 4 * 16384 + off) = hi;
        *(uint32_t*)(smem + 5 * 16384 + off) = lo;
    }

#pragma unroll 1
    for (int L = 0; L < 2; L++) {
        const float* bias = L ? b3 : b2;

        // ================= fused mainloop: h + ax + ay, 2-term each, one chunk stream =================
        float acc[16][4], accx[16][4], accy[16][4];
#pragma unroll
        for (int j = 0; j < 16; j++) {
            acc[j][0] = acc[j][1] = acc[j][2] = acc[j][3] = 0.f;
            accx[j][0] = accx[j][1] = accx[j][2] = accx[j][3] = 0.f;
            accy[j][0] = accy[j][1] = accy[j][2] = accy[j][3] = 0.f;
        }

#pragma unroll 1
        for (int it = 0; it < 16; it++) {
            CP_WAIT0();
            __syncthreads();
            if (it < 15)      copy8K(sb, L, it + 1, (it + 1) & 1, tid);
            else if (L == 0)  copy8K(sb, 1, 0, 0, tid);   // next layer chunk0
            CP_COMMIT();

            const char* pa = smem + (it * 2 + tm) * 512 + lane * 16;
            uint4 aH = *(const uint4*)(pa);
            uint4 aL = *(const uint4*)(pa + 16384);
            uint4 xH = *(const uint4*)(pa + 2 * 16384);
            uint4 xL = *(const uint4*)(pa + 3 * 16384);
            uint4 yH = *(const uint4*)(pa + 4 * 16384);
            uint4 yL = *(const uint4*)(pa + 5 * 16384);
            const char* pb = smem + SM_B + (it & 1) * 8192 + lane * 16;
#pragma unroll
            for (int j2 = 0; j2 < 8; j2++) {
                uint4 bH = *(const uint4*)(pb + (nh * 8 + j2) * 512);
                int j = 2 * j2;
                mma16816(acc[j],      aH.x, aH.y, aH.z, aH.w, bH.x, bH.y);
                mma16816(acc[j],      aL.x, aL.y, aL.z, aL.w, bH.x, bH.y);
                mma16816(accx[j],     xH.x, xH.y, xH.z, xH.w, bH.x, bH.y);
                mma16816(accx[j],     xL.x, xL.y, xL.z, xL.w, bH.x, bH.y);
                mma16816(accy[j],     yH.x, yH.y, yH.z, yH.w, bH.x, bH.y);
                mma16816(accy[j],     yL.x, yL.y, yL.z, yL.w, bH.x, bH.y);
                mma16816(acc[j + 1],  aH.x, aH.y, aH.z, aH.w, bH.z, bH.w);
                mma16816(acc[j + 1],  aL.x, aL.y, aL.z, aL.w, bH.z, bH.w);
                mma16816(accx[j + 1], xH.x, xH.y, xH.z, xH.w, bH.z, bH.w);
                mma16816(accx[j + 1], xL.x, xL.y, xL.z, xL.w, bH.z, bH.w);
                mma16816(accy[j + 1], yH.x, yH.y, yH.z, yH.w, bH.z, bH.w);
                mma16816(accy[j + 1], yL.x, yL.y, yL.z, yL.w, bH.z, bH.w);
            }
        }
        __syncthreads();   // all mainloop act reads complete before epilogue writes

        // ================= fused epilogue =================
        float pu0 = 0.f, pu1 = 0.f, pv0 = 0.f, pv1 = 0.f;
        float px0 = 0.f, px1 = 0.f, qx0 = 0.f, qx1 = 0.f;
        float py0 = 0.f, py1 = 0.f, qy0 = 0.f, qy1 = 0.f;
#pragma unroll
        for (int j = 0; j < 16; j++) {
            int n0 = nh * 128 + j * 8 + 2 * (lane & 3);
            float2 bb = ((const float2*)bias)[n0 >> 1];
            float h0 = tanhf(acc[j][0] + bb.x);
            float h1 = tanhf(acc[j][1] + bb.y);
            float h2 = tanhf(acc[j][2] + bb.x);
            float h3 = tanhf(acc[j][3] + bb.y);
            float g0 = 1.f - h0 * h0, g1 = 1.f - h1 * h1;
            float g2 = 1.f - h2 * h2, g3 = 1.f - h3 * h3;
            float ax0 = g0 * accx[j][0], ax1 = g1 * accx[j][1];
            float ax2 = g2 * accx[j][2], ax3 = g3 * accx[j][3];
            float ay0 = g0 * accy[j][0], ay1 = g1 * accy[j][1];
            float ay2 = g2 * accy[j][2], ay3 = g3 * accy[j][3];
            if (L == 0) {
                int kk = n0 & 15, tkp = n0 >> 4;
                int qk = (kk >= 8) ? 2 : 0;
                int offL = (tkp * 2 + tm) * 512 + lane * 16 + qk * 4;
                uint32_t hi, lo;
                split2(h0, h1, hi, lo);
                *(uint32_t*)(smem + 0 * 16384 + offL) = hi;
                *(uint32_t*)(smem + 1 * 16384 + offL) = lo;
                split2(h2, h3, hi, lo);
                *(uint32_t*)(smem + 0 * 16384 + offL + 4) = hi;
                *(uint32_t*)(smem + 1 * 16384 + offL + 4) = lo;
                split2(ax0, ax1, hi, lo);
                *(uint32_t*)(smem + 2 * 16384 + offL) = hi;
                *(uint32_t*)(smem + 3 * 16384 + offL) = lo;
                split2(ax2, ax3, hi, lo);
                *(uint32_t*)(smem + 2 * 16384 + offL + 4) = hi;
                *(uint32_t*)(smem + 3 * 16384 + offL + 4) = lo;
                split2(ay0, ay1, hi, lo);
                *(uint32_t*)(smem + 4 * 16384 + offL) = hi;
                *(uint32_t*)(smem + 5 * 16384 + offL) = lo;
                split2(ay2, ay3, hi, lo);
                *(uint32_t*)(smem + 4 * 16384 + offL + 4) = hi;
                *(uint32_t*)(smem + 5 * 16384 + offL + 4) = lo;
            } else {
                float2 wo0 = ((const float2*)Wo)[n0];
                float2 wo1 = ((const float2*)Wo)[n0 + 1];
                pu0 += h0 * wo0.x + h1 * wo1.x;   pv0 += h0 * wo0.y + h1 * wo1.y;
                pu1 += h2 * wo0.x + h3 * wo1.x;   pv1 += h2 * wo0.y + h3 * wo1.y;
                px0 += ax0 * wo0.x + ax1 * wo1.x; qx0 += ax0 * wo0.y + ax1 * wo1.y;
                px1 += ax2 * wo0.x + ax3 * wo1.x; qx1 += ax2 * wo0.y + ax3 * wo1.y;
                py0 += ay0 * wo0.x + ay1 * wo1.x; qy0 += ay0 * wo0.y + ay1 * wo1.y;
                py1 += ay2 * wo0.x + ay3 * wo1.x; qy1 += ay2 * wo0.y + ay3 * wo1.y;
            }
        }
        if (L == 1) {
#pragma unroll
            for (int off = 1; off <= 2; off <<= 1) {
                pu0 += __shfl_xor_sync(~0u, pu0, off); pv0 += __shfl_xor_sync(~0u, pv0, off);
                pu1 += __shfl_xor_sync(~0u, pu1, off); pv1 += __shfl_xor_sync(~0u, pv1, off);
                px0 += __shfl_xor_sync(~0u, px0, off); qx0 += __shfl_xor_sync(~0u, qx0, off);
                px1 += __shfl_xor_sync(~0u, px1, off); qx1 += __shfl_xor_sync(~0u, qx1, off);
                py0 += __shfl_xor_sync(~0u, py0, off); qy0 += __shfl_xor_sync(~0u, qy0, off);
                py1 += __shfl_xor_sync(~0u, py1, off); qy1 += __shfl_xor_sync(~0u, qy1, off);
            }
            if ((lane & 3) == 0) {
                int mlo = tm * 16 + (lane >> 2);
                atomicAdd(&so[0 * 32 + mlo], pu0);  atomicAdd(&so[0 * 32 + mlo + 8], pu1);
                atomicAdd(&so[1 * 32 + mlo], pv0);  atomicAdd(&so[1 * 32 + mlo + 8], pv1);
                atomicAdd(&so[2 * 32 + mlo], px0);  atomicAdd(&so[2 * 32 + mlo + 8], px1);
                atomicAdd(&so[3 * 32 + mlo], qx0);  atomicAdd(&so[3 * 32 + mlo + 8], qx1);
                atomicAdd(&so[4 * 32 + mlo], py0);  atomicAdd(&so[4 * 32 + mlo + 8], py1);
                atomicAdd(&so[5 * 32 + mlo], qy0);  atomicAdd(&so[5 * 32 + mlo + 8], qy1);
            }
        }
        __syncthreads();
    }

    // ---------------- final: stress transform ----------------
    if (tid < PPB) {
        float u   = so[0 * 32 + tid] + bo[0];
        float v   = so[1 * 32 + tid] + bo[1];
        float u_x = so[2 * 32 + tid], v_x = so[3 * 32 + tid];
        float u_y = so[4 * 32 + tid], v_y = so[5 * 32 + tid];
        float u_xy = u_y + v_x;
        float sx  = C11f * u_x + C12f * v_y;
        float sy  = C12f * u_x + C11f * v_y;
        float sxy = C33f * u_xy;
        float sed = 0.5f * (sx * u_x + sy * v_y + sxy * u_xy);
        int p = pbase + tid;
        out[p]            = u;
        out[NPTS + p]     = v;
        out[2 * NPTS + p] = sx;
        out[3 * NPTS + p] = sy;
        out[4 * NPTS + p] = sxy;
        out[5 * NPTS + p] = sed;
    }
}

// ---------------- launcher ----------------
extern "C" void kernel_launch(void* const* d_in, const int* in_sizes, int n_in,
                              void* d_out, int out_size)
{
    const float* X  = (const float*)d_in[0];
    const float* W1 = (const float*)d_in[1];
    const float* b1 = (const float*)d_in[2];
    const float* W2 = (const float*)d_in[3];
    const float* b2 = (const float*)d_in[4];
    const float* W3 = (const float*)d_in[5];
    const float* b3 = (const float*)d_in[6];
    const float* Wo = (const float*)d_in[7];
    const float* bo = (const float*)d_in[8];
    float* out = (float*)d_out;

    static bool attr_set = false;
    if (!attr_set) {
        cudaFuncSetAttribute(pinn_mma, cudaFuncAttributeMaxDynamicSharedMemorySize, SMEM_BYTES);
        attr_set = true;
    }

    prep_weights<<<512, 256>>>(W2, W3);
    pinn_mma<<<NPTS / PPB, NTHREADS, SMEM_BYTES>>>(X, W1, b1, b2, b3, Wo, bo, out);
}

// round 17
// speedup vs baseline: 2.0310x; 1.0172x over previous
#include <cuda_runtime.h>
#include <cuda_fp16.h>
#include <cstdint>

#define NPTS 262144
#define HID  256
#define PPB  32
#define NTHREADS 128

#define C11f 1.0989010989010990f
#define C12f 0.3296703296703297f
#define C33f 0.3846153846153846f

// B fragments: [L][tk16][split(hi/lo)][tn2(16)][t(32)] -> uint4 = frag(2*tn2) ‖ frag(2*tn2+1)
__device__ __align__(16) uint4 g_Bf[2][16][2][16][32];   // 1 MB

// ---------------- SMEM layout (bytes) ----------------
// act arrays, 16384 B each: 0 h_hi, 1 h_lo, 2 ax_hi, 3 ax_lo, 4 ay_hi, 5 ay_lo
//   addr: (tk*2+tmm)*512 + t*16 + q*4
// B slot: two 8 KB halves (hi chunks only)
#define SM_B   98304
#define SM_OUT 114688     // float[6][32]
#define SMEM_BYTES 115456

__device__ __forceinline__ uint32_t smem_u32(const void* p) {
    uint32_t a;
    asm("{ .reg .u64 t; cvta.to.shared.u64 t, %1; cvt.u32.u64 %0, t; }" : "=r"(a) : "l"(p));
    return a;
}

__device__ __forceinline__ void mma16816(float* c, uint32_t a0, uint32_t a1, uint32_t a2, uint32_t a3,
                                         uint32_t b0, uint32_t b1) {
    asm volatile(
        "mma.sync.aligned.m16n8k16.row.col.f32.f16.f16.f32 "
        "{%0,%1,%2,%3},{%4,%5,%6,%7},{%8,%9},{%0,%1,%2,%3};"
        : "+f"(c[0]), "+f"(c[1]), "+f"(c[2]), "+f"(c[3])
        : "r"(a0), "r"(a1), "r"(a2), "r"(a3), "r"(b0), "r"(b1));
}

// tanh(z) = 1 - 2/(exp(2z)+1)  via MUFU ex2 + rcp; rel err ~2^-21, correct at +-inf
__device__ __forceinline__ float fast_tanh(float z) {
    float e, r;
    asm("ex2.approx.f32 %0, %1;" : "=f"(e) : "f"(z * 2.8853900817779268f));  // 2z*log2(e)
    asm("rcp.approx.f32 %0, %1;" : "=f"(r) : "f"(e + 1.f));
    return fmaf(-2.f, r, 1.f);
}

__device__ __forceinline__ void split2(float v0, float v1, uint32_t& hi, uint32_t& lo) {
    __half h0 = __float2half_rn(v0), h1 = __float2half_rn(v1);
    __half l0 = __float2half_rn(v0 - __half2float(h0));
    __half l1 = __float2half_rn(v1 - __half2float(h1));
    __half2 hh = __halves2half2(h0, h1), ll = __halves2half2(l0, l1);
    hi = *(uint32_t*)&hh;
    lo = *(uint32_t*)&ll;
}

__device__ __forceinline__ void cpasync16(uint32_t dst, const void* src) {
    asm volatile("cp.async.cg.shared.global [%0], [%1], 16;" :: "r"(dst), "l"(src));
}
#define CP_COMMIT() asm volatile("cp.async.commit_group;" ::: "memory")
#define CP_WAIT0()  asm volatile("cp.async.wait_group 0;" ::: "memory")

__device__ __forceinline__ void copy8K(uint32_t sb, int L, int tk, int buf, int tid) {
    uint32_t dst = sb + SM_B + buf * 8192 + tid * 16;
    const char* src = (const char*)g_Bf + L * 262144 + tk * 16384 + tid * 16;
#pragma unroll
    for (int i = 0; i < 4; i++) cpasync16(dst + i * 2048, src + i * 2048);
}

// ---------------- prep: weights -> paired fragment order, hi/lo split ----------------
__global__ void prep_weights(const float* __restrict__ W2, const float* __restrict__ W3) {
    int L = blockIdx.x >> 8;
    int k = blockIdx.x & 255;
    int n = threadIdx.x;
    float w = (L ? W3 : W2)[k * HID + n];
    __half hi = __float2half_rn(w);
    __half lo = __float2half_rn(w - __half2float(hi));
    int tk = k >> 4, kk = k & 15, tn = n >> 3;
    int t = (n & 7) * 4 + ((kk & 7) >> 1);
    int r = (kk >= 8) ? 1 : 0, hsel = kk & 1;
    __half* base = (__half*)g_Bf;
    int i0 = ((((L * 16 + tk) * 2 + 0) * 16 + (tn >> 1)) * 32 + t) * 8 + (tn & 1) * 4 + r * 2 + hsel;
    int i1 = ((((L * 16 + tk) * 2 + 1) * 16 + (tn >> 1)) * 32 + t) * 8 + (tn & 1) * 4 + r * 2 + hsel;
    base[i0] = hi;
    base[i1] = lo;
}

// ---------------- main fused kernel ----------------
__global__ void __launch_bounds__(NTHREADS, 2)
pinn_mma(const float* __restrict__ X,
         const float* __restrict__ W1, const float* __restrict__ b1,
         const float* __restrict__ b2, const float* __restrict__ b3,
         const float* __restrict__ Wo, const float* __restrict__ bo,
         float* __restrict__ out)
{
    extern __shared__ char smem[];
    const uint32_t sb = smem_u32(smem);
    const int tid = threadIdx.x, w = tid >> 5, lane = tid & 31;
    const int tm = w >> 1, nh = w & 1;
    const int pbase = blockIdx.x * PPB;
    float* so = (float*)(smem + SM_OUT);

    for (int i = tid; i < 192; i += NTHREADS) so[i] = 0.f;

    copy8K(sb, 0, 0, 0, tid);
    CP_COMMIT();

    // ---------------- layer 1 ----------------
    for (int idx = tid; idx < PPB * 128; idx += NTHREADS) {
        int m = idx >> 7, n0 = (idx & 127) * 2;
        float2 xy = ((const float2*)X)[pbase + m];
        float wx0 = W1[n0], wx1 = W1[n0 + 1];
        float wy0 = W1[HID + n0], wy1 = W1[HID + n0 + 1];
        float z0 = fmaf(xy.x, wx0, fmaf(xy.y, wy0, b1[n0]));
        float z1 = fmaf(xy.x, wx1, fmaf(xy.y, wy1, b1[n0 + 1]));
        float h0 = fast_tanh(z0), h1 = fast_tanh(z1);
        float g0 = 1.f - h0 * h0, g1 = 1.f - h1 * h1;
        int kk = n0 & 15, tkp = n0 >> 4;
        int tp = (m & 7) * 4 + ((kk & 7) >> 1);
        int q = (((m & 15) >= 8) ? 1 : 0) + ((kk >= 8) ? 2 : 0);
        int off = (tkp * 2 + (m >> 4)) * 512 + tp * 16 + q * 4;
        uint32_t hi, lo;
        split2(h0, h1, hi, lo);
        *(uint32_t*)(smem + 0 * 16384 + off) = hi;
        *(uint32_t*)(smem + 1 * 16384 + off) = lo;
        split2(g0 * wx0, g1 * wx1, hi, lo);
        *(uint32_t*)(smem + 2 * 16384 + off) = hi;
        *(uint32_t*)(smem + 3 * 16384 + off) = lo;
        split2(g0 * wy0, g1 * wy1, hi, lo);
        *(uint32_t*)(smem + 4 * 16384 + off) = hi;
        *(uint32_t*)(smem + 5 * 16384 + off) = lo;
    }

#pragma unroll 1
    for (int L = 0; L < 2; L++) {
        const float* bias = L ? b3 : b2;

        // ================= fused mainloop: h + ax + ay, 2-term each =================
        float acc[16][4], accx[16][4], accy[16][4];
#pragma unroll
        for (int j = 0; j < 16; j++) {
            acc[j][0] = acc[j][1] = acc[j][2] = acc[j][3] = 0.f;
            accx[j][0] = accx[j][1] = accx[j][2] = accx[j][3] = 0.f;
            accy[j][0] = accy[j][1] = accy[j][2] = accy[j][3] = 0.f;
        }

#pragma unroll 1
        for (int it = 0; it < 16; it++) {
            CP_WAIT0();
            __syncthreads();
            if (it < 15)      copy8K(sb, L, it + 1, (it + 1) & 1, tid);
            else if (L == 0)  copy8K(sb, 1, 0, 0, tid);
            CP_COMMIT();

            const char* pa = smem + (it * 2 + tm) * 512 + lane * 16;
            uint4 aH = *(const uint4*)(pa);
            uint4 aL = *(const uint4*)(pa + 16384);
            uint4 xH = *(const uint4*)(pa + 2 * 16384);
            uint4 xL = *(const uint4*)(pa + 3 * 16384);
            uint4 yH = *(const uint4*)(pa + 4 * 16384);
            uint4 yL = *(const uint4*)(pa + 5 * 16384);
            const char* pb = smem + SM_B + (it & 1) * 8192 + lane * 16;
#pragma unroll
            for (int j2 = 0; j2 < 8; j2++) {
                uint4 bH = *(const uint4*)(pb + (nh * 8 + j2) * 512);
                int j = 2 * j2;
                mma16816(acc[j],      aH.x, aH.y, aH.z, aH.w, bH.x, bH.y);
                mma16816(acc[j],      aL.x, aL.y, aL.z, aL.w, bH.x, bH.y);
                mma16816(accx[j],     xH.x, xH.y, xH.z, xH.w, bH.x, bH.y);
                mma16816(accx[j],     xL.x, xL.y, xL.z, xL.w, bH.x, bH.y);
                mma16816(accy[j],     yH.x, yH.y, yH.z, yH.w, bH.x, bH.y);
                mma16816(accy[j],     yL.x, yL.y, yL.z, yL.w, bH.x, bH.y);
                mma16816(acc[j + 1],  aH.x, aH.y, aH.z, aH.w, bH.z, bH.w);
                mma16816(acc[j + 1],  aL.x, aL.y, aL.z, aL.w, bH.z, bH.w);
                mma16816(accx[j + 1], xH.x, xH.y, xH.z, xH.w, bH.z, bH.w);
                mma16816(accx[j + 1], xL.x, xL.y, xL.z, xL.w, bH.z, bH.w);
                mma16816(accy[j + 1], yH.x, yH.y, yH.z, yH.w, bH.z, bH.w);
                mma16816(accy[j + 1], yL.x, yL.y, yL.z, yL.w, bH.z, bH.w);
            }
        }
        __syncthreads();

        // ================= fused epilogue =================
        float pu0 = 0.f, pu1 = 0.f, pv0 = 0.f, pv1 = 0.f;
        float px0 = 0.f, px1 = 0.f, qx0 = 0.f, qx1 = 0.f;
        float py0 = 0.f, py1 = 0.f, qy0 = 0.f, qy1 = 0.f;
#pragma unroll
        for (int j = 0; j < 16; j++) {
            int n0 = nh * 128 + j * 8 + 2 * (lane & 3);
            float2 bb = ((const float2*)bias)[n0 >> 1];
            float h0 = fast_tanh(acc[j][0] + bb.x);
            float h1 = fast_tanh(acc[j][1] + bb.y);
            float h2 = fast_tanh(acc[j][2] + bb.x);
            float h3 = fast_tanh(acc[j][3] + bb.y);
            float g0 = 1.f - h0 * h0, g1 = 1.f - h1 * h1;
            float g2 = 1.f - h2 * h2, g3 = 1.f - h3 * h3;
            float ax0 = g0 * accx[j][0], ax1 = g1 * accx[j][1];
            float ax2 = g2 * accx[j][2], ax3 = g3 * accx[j][3];
            float ay0 = g0 * accy[j][0], ay1 = g1 * accy[j][1];
            float ay2 = g2 * accy[j][2], ay3 = g3 * accy[j][3];
            if (L == 0) {
                int kk = n0 & 15, tkp = n0 >> 4;
                int qk = (kk >= 8) ? 2 : 0;
                int offL = (tkp * 2 + tm) * 512 + lane * 16 + qk * 4;   // 8B-aligned
                uint32_t hiA, loA, hiB, loB;
                split2(h0, h1, hiA, loA);
                split2(h2, h3, hiB, loB);
                *(uint2*)(smem + 0 * 16384 + offL) = make_uint2(hiA, hiB);
                *(uint2*)(smem + 1 * 16384 + offL) = make_uint2(loA, loB);
                split2(ax0, ax1, hiA, loA);
                split2(ax2, ax3, hiB, loB);
                *(uint2*)(smem + 2 * 16384 + offL) = make_uint2(hiA, hiB);
                *(uint2*)(smem + 3 * 16384 + offL) = make_uint2(loA, loB);
                split2(ay0, ay1, hiA, loA);
                split2(ay2, ay3, hiB, loB);
                *(uint2*)(smem + 4 * 16384 + offL) = make_uint2(hiA, hiB);
                *(uint2*)(smem + 5 * 16384 + offL) = make_uint2(loA, loB);
            } else {
                float2 wo0 = ((const float2*)Wo)[n0];
                float2 wo1 = ((const float2*)Wo)[n0 + 1];
                pu0 += h0 * wo0.x + h1 * wo1.x;   pv0 += h0 * wo0.y + h1 * wo1.y;
                pu1 += h2 * wo0.x + h3 * wo1.x;   pv1 += h2 * wo0.y + h3 * wo1.y;
                px0 += ax0 * wo0.x + ax1 * wo1.x; qx0 += ax0 * wo0.y + ax1 * wo1.y;
                px1 += ax2 * wo0.x + ax3 * wo1.x; qx1 += ax2 * wo0.y + ax3 * wo1.y;
                py0 += ay0 * wo0.x + ay1 * wo1.x; qy0 += ay0 * wo0.y + ay1 * wo1.y;
                py1 += ay2 * wo0.x + ay3 * wo1.x; qy1 += ay2 * wo0.y + ay3 * wo1.y;
            }
        }
        if (L == 1) {
#pragma unroll
            for (int off = 1; off <= 2; off <<= 1) {
                pu0 += __shfl_xor_sync(~0u, pu0, off); pv0 += __shfl_xor_sync(~0u, pv0, off);
                pu1 += __shfl_xor_sync(~0u, pu1, off); pv1 += __shfl_xor_sync(~0u, pv1, off);
                px0 += __shfl_xor_sync(~0u, px0, off); qx0 += __shfl_xor_sync(~0u, qx0, off);
                px1 += __shfl_xor_sync(~0u, px1, off); qx1 += __shfl_xor_sync(~0u, qx1, off);
                py0 += __shfl_xor_sync(~0u, py0, off); qy0 += __shfl_xor_sync(~0u, qy0, off);
                py1 += __shfl_xor_sync(~0u, py1, off); qy1 += __shfl_xor_sync(~0u, qy1, off);
            }
            if ((lane & 3) == 0) {
                int mlo = tm * 16 + (lane >> 2);
                atomicAdd(&so[0 * 32 + mlo], pu0);  atomicAdd(&so[0 * 32 + mlo + 8], pu1);
                atomicAdd(&so[1 * 32 + mlo], pv0);  atomicAdd(&so[1 * 32 + mlo + 8], pv1);
                atomicAdd(&so[2 * 32 + mlo], px0);  atomicAdd(&so[2 * 32 + mlo + 8], px1);
                atomicAdd(&so[3 * 32 + mlo], qx0);  atomicAdd(&so[3 * 32 + mlo + 8], qx1);
                atomicAdd(&so[4 * 32 + mlo], py0);  atomicAdd(&so[4 * 32 + mlo + 8], py1);
                atomicAdd(&so[5 * 32 + mlo], qy0);  atomicAdd(&so[5 * 32 + mlo + 8], qy1);
            }
        }
        __syncthreads();
    }

    // ---------------- final: stress transform ----------------
    if (tid < PPB) {
        float u   = so[0 * 32 + tid] + bo[0];
        float v   = so[1 * 32 + tid] + bo[1];
        float u_x = so[2 * 32 + tid], v_x = so[3 * 32 + tid];
        float u_y = so[4 * 32 + tid], v_y = so[5 * 32 + tid];
        float u_xy = u_y + v_x;
        float sx  = C11f * u_x + C12f * v_y;
        float sy  = C12f * u_x + C11f * v_y;
        float sxy = C33f * u_xy;
        float sed = 0.5f * (sx * u_x + sy * v_y + sxy * u_xy);
        int p = pbase + tid;
        out[p]            = u;
        out[NPTS + p]     = v;
        out[2 * NPTS + p] = sx;
        out[3 * NPTS + p] = sy;
        out[4 * NPTS + p] = sxy;
        out[5 * NPTS + p] = sed;
    }
}

// ---------------- launcher ----------------
extern "C" void kernel_launch(void* const* d_in, const int* in_sizes, int n_in,
                              void* d_out, int out_size)
{
    const float* X  = (const float*)d_in[0];
    const float* W1 = (const float*)d_in[1];
    const float* b1 = (const float*)d_in[2];
    const float* W2 = (const float*)d_in[3];
    const float* b2 = (const float*)d_in[4];
    const float* W3 = (const float*)d_in[5];
    const float* b3 = (const float*)d_in[6];
    const float* Wo = (const float*)d_in[7];
    const float* bo = (const float*)d_in[8];
    float* out = (float*)d_out;

    static bool attr_set = false;
    if (!attr_set) {
        cudaFuncSetAttribute(pinn_mma, cudaFuncAttributeMaxDynamicSharedMemorySize, SMEM_BYTES);
        attr_set = true;
    }

    prep_weights<<<512, 256>>>(W2, W3);
    pinn_mma<<<NPTS / PPB, NTHREADS, SMEM_BYTES>>>(X, W1, b1, b2, b3, Wo, bo, out);
}